// round 3
// baseline (speedup 1.0000x reference)
#include <cuda_runtime.h>
#include <cuda_bf16.h>
#include <cstdint>

// HeteLinear: out[n] = x[n] @ W[x_type[n]] + b[x_type[n]]
// N=262144, IN=OUT=128, T=8, fp32.
// Grouped GEMM on mma.sync (HMMA bf16, sm_80+ PTX -> compiles for plain sm_103),
// 3-product bf16 hi/lo split for fp32-grade accuracy, persistent CTAs with
// register-prefetch pipelining of the row gather.

#define NMAX    262144
#define TT      8
#define DIM     128
#define TILE_M  128
#define GT      256
#define NWARP   8
#define LDE     136                 // padded row length (bf16 elems): 272B = 17*16B
#define LDB     (LDE * 2)           // 272 bytes
#define IMG_BYTES (DIM * LDE * 2)   // 34816
#define IMG_U4    (IMG_BYTES / 16)  // 2176

// smem layout (bytes)
#define S_AHI   0
#define S_ALO   34816
#define S_WHI   69632
#define S_WLO   104448
#define S_BIAS  139264              // float[2][128]
#define S_TOTAL (S_BIAS + 1024)

// ---------------- device globals ----------------
__device__ int g_counts[TT];
__device__ int g_offsets[TT + 1];
__device__ int g_cursor[TT];
__device__ int g_tileBase[TT + 1];
__device__ int g_perm[NMAX];
__device__ __align__(16) uint8_t g_Whi[TT][IMG_BYTES];
__device__ __align__(16) uint8_t g_Wlo[TT][IMG_BYTES];

// ---------------- helpers ----------------
__device__ __forceinline__ uint32_t smem_u32(const void* p) {
    uint32_t a;
    asm("{ .reg .u64 t; cvta.to.shared.u64 t, %1; cvt.u32.u64 %0, t; }" : "=r"(a) : "l"(p));
    return a;
}
__device__ __forceinline__ void ldsm4(uint32_t (&r)[4], uint32_t addr) {
    asm volatile("ldmatrix.sync.aligned.m8n8.x4.shared.b16 {%0,%1,%2,%3}, [%4];"
                 : "=r"(r[0]), "=r"(r[1]), "=r"(r[2]), "=r"(r[3]) : "r"(addr));
}
__device__ __forceinline__ void mma16816(float (&c)[4], const uint32_t (&a)[4],
                                         uint32_t b0, uint32_t b1) {
    asm volatile("mma.sync.aligned.m16n8k16.row.col.f32.bf16.bf16.f32 "
                 "{%0,%1,%2,%3}, {%4,%5,%6,%7}, {%8,%9}, {%0,%1,%2,%3};"
                 : "+f"(c[0]), "+f"(c[1]), "+f"(c[2]), "+f"(c[3])
                 : "r"(a[0]), "r"(a[1]), "r"(a[2]), "r"(a[3]), "r"(b0), "r"(b1));
}
__device__ __forceinline__ uint32_t pkbf(__nv_bfloat16 a, __nv_bfloat16 b) {
    return (uint32_t)__bfloat16_as_ushort(a) | ((uint32_t)__bfloat16_as_ushort(b) << 16);
}

// ---------------- compaction ----------------
__global__ void k_init() { if (threadIdx.x < TT) g_counts[threadIdx.x] = 0; }

__global__ void k_hist(const int* __restrict__ xt, int n) {
    __shared__ int h[TT];
    if (threadIdx.x < TT) h[threadIdx.x] = 0;
    __syncthreads();
    for (int i = blockIdx.x * blockDim.x + threadIdx.x; i < n; i += gridDim.x * blockDim.x)
        atomicAdd(&h[xt[i]], 1);
    __syncthreads();
    if (threadIdx.x < TT) atomicAdd(&g_counts[threadIdx.x], h[threadIdx.x]);
}
__global__ void k_scan() {
    if (threadIdx.x == 0) {
        int o = 0, tb = 0;
        g_offsets[0] = 0; g_tileBase[0] = 0;
        for (int t = 0; t < TT; t++) {
            int c = g_counts[t];
            g_cursor[t] = o;
            o += c; g_offsets[t + 1] = o;
            tb += (c + TILE_M - 1) / TILE_M;
            g_tileBase[t + 1] = tb;
        }
    }
}
__global__ void k_scatter(const int* __restrict__ xt, int n) {
    int lane = threadIdx.x & 31;
    for (int i = blockIdx.x * blockDim.x + threadIdx.x; i < n; i += gridDim.x * blockDim.x) {
        int m = xt[i];
        #pragma unroll
        for (int t = 0; t < TT; t++) {
            unsigned mask = __ballot_sync(0xffffffffu, m == t);
            if (mask) {
                int leader = __ffs(mask) - 1;
                int pos = 0;
                if (lane == leader) pos = atomicAdd(&g_cursor[t], __popc(mask));
                pos = __shfl_sync(0xffffffffu, pos, leader);
                if (m == t) g_perm[pos + __popc(mask & ((1u << lane) - 1u))] = i;
            }
        }
    }
}

// ---------------- W prep: [n][k] K-major padded bf16 hi/lo images ----------------
__global__ void k_prep(const float* __restrict__ W) {
    int t = blockIdx.x;
    __nv_bfloat16* hi = (__nv_bfloat16*)g_Whi[t];
    __nv_bfloat16* lo = (__nv_bfloat16*)g_Wlo[t];
    for (int idx = threadIdx.x; idx < DIM * DIM; idx += blockDim.x) {
        int n = idx >> 7;
        int k = idx & 127;
        float w = W[((size_t)t * DIM + k) * DIM + n];
        __nv_bfloat16 h = __float2bfloat16_rn(w);
        __nv_bfloat16 l = __float2bfloat16_rn(w - __bfloat162float(h));
        hi[n * LDE + k] = h;
        lo[n * LDE + k] = l;
    }
}

// ---------------- GEMM pieces ----------------
__device__ __forceinline__ void copyW(int t, uint8_t* smem, int tid) {
    const uint4* shi = (const uint4*)g_Whi[t];
    const uint4* slo = (const uint4*)g_Wlo[t];
    uint4* dhi = (uint4*)(smem + S_WHI);
    uint4* dlo = (uint4*)(smem + S_WLO);
    #pragma unroll 4
    for (int i = tid; i < IMG_U4; i += GT) { dhi[i] = shi[i]; dlo[i] = slo[i]; }
}

__device__ __forceinline__ void cvtStore(const uint4* v, uint8_t* smem, int warp, int lane) {
    #pragma unroll
    for (int rr = 0; rr < 16; rr++) {
        float4 f = *(const float4*)&v[rr];
        __nv_bfloat16 h0 = __float2bfloat16_rn(f.x), h1 = __float2bfloat16_rn(f.y);
        __nv_bfloat16 h2 = __float2bfloat16_rn(f.z), h3 = __float2bfloat16_rn(f.w);
        __nv_bfloat16 l0 = __float2bfloat16_rn(f.x - __bfloat162float(h0));
        __nv_bfloat16 l1 = __float2bfloat16_rn(f.y - __bfloat162float(h1));
        __nv_bfloat16 l2 = __float2bfloat16_rn(f.z - __bfloat162float(h2));
        __nv_bfloat16 l3 = __float2bfloat16_rn(f.w - __bfloat162float(h3));
        uint32_t offB = (uint32_t)(warp * 16 + rr) * LDB + (uint32_t)lane * 8;
        *(uint2*)(smem + S_AHI + offB) = make_uint2(pkbf(h0, h1), pkbf(h2, h3));
        *(uint2*)(smem + S_ALO + offB) = make_uint2(pkbf(l0, l1), pkbf(l2, l3));
    }
}

__global__ __launch_bounds__(GT, 1)
void k_gemm(const float* __restrict__ x,
            const float* __restrict__ b,
            float* __restrict__ out)
{
    extern __shared__ uint8_t smem[];
    const int tid  = threadIdx.x;
    const int warp = tid >> 5;
    const int lane = tid & 31;

    const uint32_t sbase = smem_u32(smem);
    float* biasS = (float*)(smem + S_BIAS);

    int tb[TT + 1], off[TT + 1];
    #pragma unroll
    for (int i = 0; i <= TT; i++) { tb[i] = g_tileBase[i]; off[i] = g_offsets[i]; }

    const int total = tb[TT];
    const int per   = (total + gridDim.x - 1) / gridDim.x;
    const int i0    = blockIdx.x * per;
    const int i1    = min(i0 + per, total);
    if (i0 >= i1) return;

    // lane-constant ldmatrix offsets
    const uint32_t aOff = (uint32_t)(warp * 16 + (lane & 15)) * LDB + (uint32_t)(lane >> 4) * 16;
    const uint32_t bOff = (uint32_t)(((lane & 7) + ((lane & 16) ? 8 : 0))) * LDB
                        + (uint32_t)((lane >> 3) & 1) * 16;

    float acc[16][4];
    #pragma unroll
    for (int j = 0; j < 16; j++)
        #pragma unroll
        for (int q = 0; q < 4; q++) acc[j][q] = 0.f;

    int   rcur = -1, cur_type = -1;
    uint4 v[16];

    // ---- prologue: stage tile i0 ----
    {
        int t = 0;
        #pragma unroll
        for (int s = 1; s < TT; s++) t += (i0 >= tb[s]);
        copyW(t, smem, tid); cur_type = t;
        int segStart = off[t] + (i0 - tb[t]) * TILE_M;
        int nr       = min(TILE_M, off[t + 1] - segStart);
        if (lane < 16) {
            int idx = warp * 16 + lane;
            rcur = (idx < nr) ? g_perm[segStart + idx] : -1;
        }
        if (tid < DIM) biasS[(i0 & 1) * DIM + tid] = b[(size_t)t * DIM + tid];
        #pragma unroll
        for (int rr = 0; rr < 16; rr++) {
            int row = __shfl_sync(0xffffffffu, rcur, rr);
            uint4 vv = make_uint4(0, 0, 0, 0);
            if (row >= 0) vv = ((const uint4*)x)[(size_t)row * 32 + lane];
            v[rr] = vv;
        }
        cvtStore(v, smem, warp, lane);
        __syncthreads();
    }

    for (int i = i0; i < i1; i++) {
        // ---- prefetch tile i+1 into registers (consumed after mma) ----
        int   nt = -1, rnext = -1;
        float bval = 0.f;
        if (i + 1 < i1) {
            nt = 0;
            #pragma unroll
            for (int s = 1; s < TT; s++) nt += ((i + 1) >= tb[s]);
            int segStart = off[nt] + (i + 1 - tb[nt]) * TILE_M;
            int nr       = min(TILE_M, off[nt + 1] - segStart);
            if (lane < 16) {
                int idx = warp * 16 + lane;
                rnext = (idx < nr) ? g_perm[segStart + idx] : -1;
            }
            #pragma unroll
            for (int rr = 0; rr < 16; rr++) {
                int row = __shfl_sync(0xffffffffu, rnext, rr);
                uint4 vv = make_uint4(0, 0, 0, 0);
                if (row >= 0) vv = ((const uint4*)x)[(size_t)row * 32 + lane];
                v[rr] = vv;
            }
            if (tid < DIM) bval = b[(size_t)nt * DIM + tid];
        }

        // ---- MMA: 3 products x 8 k-steps x 16 n-tiles ----
        #pragma unroll
        for (int p = 0; p < 3; p++) {
            const uint32_t aBase = sbase + (p == 2 ? S_ALO : S_AHI) + aOff;
            const uint32_t bBase = sbase + (p == 1 ? S_WLO : S_WHI) + bOff;
            #pragma unroll
            for (int kk = 0; kk < 8; kk++) {
                uint32_t a[4];
                ldsm4(a, aBase + kk * 32);
                #pragma unroll
                for (int jj = 0; jj < 8; jj++) {
                    uint32_t bb[4];
                    ldsm4(bb, bBase + (uint32_t)jj * (16 * LDB) + kk * 32);
                    mma16816(acc[2 * jj],     a, bb[0], bb[1]);
                    mma16816(acc[2 * jj + 1], a, bb[2], bb[3]);
                }
            }
        }
        __syncthreads();   // all warps done reading A (and W) images

        if (nt >= 0) {
            if (nt != cur_type) { copyW(nt, smem, tid); cur_type = nt; }
            cvtStore(v, smem, warp, lane);
            if (tid < DIM) biasS[((i + 1) & 1) * DIM + tid] = bval;
        }
        __syncthreads();   // new images/bias visible

        // ---- epilogue tile i: bias + direct stores from accum fragments ----
        {
            int g1 = __shfl_sync(0xffffffffu, rcur, lane >> 2);
            int g2 = __shfl_sync(0xffffffffu, rcur, (lane >> 2) + 8);
            const float* bS = biasS + (i & 1) * DIM;
            #pragma unroll
            for (int j = 0; j < 16; j++) {
                int col = j * 8 + (lane & 3) * 2;
                float2 bb = *(const float2*)(bS + col);
                if (g1 >= 0) {
                    float2 o = make_float2(acc[j][0] + bb.x, acc[j][1] + bb.y);
                    *(float2*)(out + (size_t)g1 * DIM + col) = o;
                }
                if (g2 >= 0) {
                    float2 o = make_float2(acc[j][2] + bb.x, acc[j][3] + bb.y);
                    *(float2*)(out + (size_t)g2 * DIM + col) = o;
                }
                acc[j][0] = acc[j][1] = acc[j][2] = acc[j][3] = 0.f;
            }
        }
        rcur = rnext;
    }
}

// ---------------- launch ----------------
extern "C" void kernel_launch(void* const* d_in, const int* in_sizes, int n_in,
                              void* d_out, int out_size)
{
    const float* x      = (const float*)d_in[0];
    const int*   x_type = (const int*)d_in[1];
    const float* W      = (const float*)d_in[2];
    const float* b      = (const float*)d_in[3];
    float*       out    = (float*)d_out;

    const int N = in_sizes[1];

    static int nsm = 0;
    if (!nsm) {
        cudaDeviceGetAttribute(&nsm, cudaDevAttrMultiProcessorCount, 0);
        if (nsm <= 0) nsm = 148;
        cudaFuncSetAttribute(k_gemm, cudaFuncAttributeMaxDynamicSharedMemorySize, S_TOTAL);
    }

    k_init<<<1, 32>>>();
    k_hist<<<256, 256>>>(x_type, N);
    k_scan<<<1, 32>>>();
    k_scatter<<<256, 256>>>(x_type, N);
    k_prep<<<TT, 256>>>(W);
    k_gemm<<<nsm, GT, S_TOTAL>>>(x, b, out);
}

// round 4
// speedup vs baseline: 1.7681x; 1.7681x over previous
#include <cuda_runtime.h>
#include <cuda_bf16.h>
#include <cstdint>

// HeteLinear: out[n] = x[n] @ W[x_type[n]] + b[x_type[n]]
// N=262144, IN=OUT=128, T=8, fp32.
// Grouped GEMM on mma.sync HMMA bf16 (sm_80+ PTX, works on plain sm_103 target),
// 3-product bf16 hi/lo split. Atomic-free compaction; persistent CTAs with
// double-buffered A images and register prefetch of the row gather.

#define NMAX    262144
#define TT      8
#define DIM     128
#define TILE_M  128
#define GT      512
#define NB      256                 // compaction blocks
#define BT      256                 // compaction threads
#define LDE     136                 // padded image row (bf16 elems): 272B
#define LDB     (LDE * 2)
#define IMG_BYTES (DIM * LDE * 2)   // 34816
#define IMG_U4    (IMG_BYTES / 16)

// gemm smem layout (bytes)
#define S_A0    0
#define S_A1    69632
#define A_LO    34816
#define S_WHI   139264
#define S_WLO   174080
#define S_BIAS  208896              // float[2][128]
#define S_ROWS  209920              // int[2][128]
#define S_TOTAL 210944

// ---------------- device globals ----------------
__device__ int g_bcount[TT * NB];
__device__ int g_bbase[TT * NB];
__device__ int g_offsets[TT + 1];
__device__ int g_tileBase[TT + 1];
__device__ int g_perm[NMAX];
__device__ __align__(16) uint8_t g_Whi[TT][IMG_BYTES];
__device__ __align__(16) uint8_t g_Wlo[TT][IMG_BYTES];

// ---------------- helpers ----------------
__device__ __forceinline__ uint32_t smem_u32(const void* p) {
    uint32_t a;
    asm("{ .reg .u64 t; cvta.to.shared.u64 t, %1; cvt.u32.u64 %0, t; }" : "=r"(a) : "l"(p));
    return a;
}
__device__ __forceinline__ void ldsm4(uint32_t (&r)[4], uint32_t addr) {
    asm volatile("ldmatrix.sync.aligned.m8n8.x4.shared.b16 {%0,%1,%2,%3}, [%4];"
                 : "=r"(r[0]), "=r"(r[1]), "=r"(r[2]), "=r"(r[3]) : "r"(addr));
}
__device__ __forceinline__ void mma16816(float (&c)[4], const uint32_t (&a)[4],
                                         uint32_t b0, uint32_t b1) {
    asm volatile("mma.sync.aligned.m16n8k16.row.col.f32.bf16.bf16.f32 "
                 "{%0,%1,%2,%3}, {%4,%5,%6,%7}, {%8,%9}, {%0,%1,%2,%3};"
                 : "+f"(c[0]), "+f"(c[1]), "+f"(c[2]), "+f"(c[3])
                 : "r"(a[0]), "r"(a[1]), "r"(a[2]), "r"(a[3]), "r"(b0), "r"(b1));
}
__device__ __forceinline__ uint32_t pkbf(__nv_bfloat16 a, __nv_bfloat16 b) {
    return (uint32_t)__bfloat16_as_ushort(a) | ((uint32_t)__bfloat16_as_ushort(b) << 16);
}

// ---------------- compaction: count / scan / scatter (atomic-light) ----------------
__global__ void k_count(const int* __restrict__ xt, int n, int seg) {
    const int bid = blockIdx.x, tid = threadIdx.x, lane = tid & 31;
    const int start = bid * seg, end = min(start + seg, n);
    __shared__ int cnt[TT];
    if (tid < TT) cnt[tid] = 0;
    __syncthreads();
    int rc[TT];
    #pragma unroll
    for (int t = 0; t < TT; t++) rc[t] = 0;
    const int rounds = (seg + BT - 1) / BT;
    for (int r = 0; r < rounds; r++) {
        int i = start + r * BT + tid;
        int m = (i < end) ? xt[i] : -1;
        #pragma unroll
        for (int t = 0; t < TT; t++) {
            unsigned mask = __ballot_sync(0xffffffffu, m == t);
            rc[t] += __popc(mask);
        }
    }
    if (lane == 0) {
        #pragma unroll
        for (int t = 0; t < TT; t++) atomicAdd(&cnt[t], rc[t]);
    }
    __syncthreads();
    if (tid < TT) g_bcount[tid * NB + bid] = cnt[tid];
}

__global__ void k_scan() {
    const int tid = threadIdx.x, warp = tid >> 5, lane = tid & 31;
    __shared__ int tot[TT];
    if (warp < TT) {
        int s = 0;
        #pragma unroll
        for (int c = 0; c < NB / 32; c++) s += g_bcount[warp * NB + c * 32 + lane];
        #pragma unroll
        for (int o = 16; o; o >>= 1) s += __shfl_xor_sync(0xffffffffu, s, o);
        if (lane == 0) tot[warp] = s;
    }
    __syncthreads();
    if (tid == 0) {
        int o = 0, tbv = 0;
        g_offsets[0] = 0; g_tileBase[0] = 0;
        for (int t = 0; t < TT; t++) {
            o += tot[t];
            g_offsets[t + 1] = o;
            tbv += (tot[t] + TILE_M - 1) / TILE_M;
            g_tileBase[t + 1] = tbv;
        }
    }
    __syncthreads();
    if (warp < TT) {
        int run = g_offsets[warp];
        #pragma unroll
        for (int c = 0; c < NB / 32; c++) {
            int v = g_bcount[warp * NB + c * 32 + lane];
            int xsc = v;
            #pragma unroll
            for (int o = 1; o < 32; o <<= 1) {
                int y = __shfl_up_sync(0xffffffffu, xsc, o);
                if (lane >= o) xsc += y;
            }
            g_bbase[warp * NB + c * 32 + lane] = run + xsc - v;
            run += __shfl_sync(0xffffffffu, xsc, 31);
        }
    }
}

__global__ void k_scatter(const int* __restrict__ xt, int n, int seg) {
    const int bid = blockIdx.x, tid = threadIdx.x, lane = tid & 31;
    const int start = bid * seg, end = min(start + seg, n);
    __shared__ int cur[TT];
    if (tid < TT) cur[tid] = g_bbase[tid * NB + bid];
    __syncthreads();
    const int rounds = (seg + BT - 1) / BT;
    for (int r = 0; r < rounds; r++) {
        int i = start + r * BT + tid;
        int m = (i < end) ? xt[i] : -1;
        #pragma unroll
        for (int t = 0; t < TT; t++) {
            unsigned mask = __ballot_sync(0xffffffffu, m == t);
            if (mask) {
                int leader = __ffs(mask) - 1;
                int pos = 0;
                if (lane == leader) pos = atomicAdd(&cur[t], __popc(mask));
                pos = __shfl_sync(0xffffffffu, pos, leader);
                if (m == t) g_perm[pos + __popc(mask & ((1u << lane) - 1u))] = i;
            }
        }
    }
}

// ---------------- W prep: [n][k] K-major padded bf16 hi/lo images ----------------
__global__ void k_prep(const float* __restrict__ W) {
    const int t = blockIdx.x, tid = threadIdx.x;
    __shared__ float ws[32][129];
    for (int kb = 0; kb < DIM; kb += 32) {
        __syncthreads();
        // coalesced load of 32 W rows (k = kb..kb+31)
        #pragma unroll
        for (int j = 0; j < 16; j++) {
            int idx = tid + j * 256;
            int r = idx >> 7, col = idx & 127;
            ws[r][col] = W[((size_t)t * DIM + kb + r) * DIM + col];
        }
        __syncthreads();
        // write image words: n-row, packed pairs of k
        const int kk = tid & 15;          // k-pair within chunk
        #pragma unroll
        for (int j = 0; j < 8; j++) {
            int nn = (tid >> 4) + j * 16;
            float w0 = ws[2 * kk][nn], w1 = ws[2 * kk + 1][nn];
            __nv_bfloat16 h0 = __float2bfloat16_rn(w0), h1 = __float2bfloat16_rn(w1);
            __nv_bfloat16 l0 = __float2bfloat16_rn(w0 - __bfloat162float(h0));
            __nv_bfloat16 l1 = __float2bfloat16_rn(w1 - __bfloat162float(h1));
            uint32_t off = (uint32_t)nn * LDB + (uint32_t)(kb + 2 * kk) * 2;
            *(uint32_t*)(g_Whi[t] + off) = pkbf(h0, h1);
            *(uint32_t*)(g_Wlo[t] + off) = pkbf(l0, l1);
        }
    }
}

// ---------------- GEMM ----------------
__device__ __forceinline__ void copyW(int t, uint8_t* smem, int tid) {
    const uint4* shi = (const uint4*)g_Whi[t];
    const uint4* slo = (const uint4*)g_Wlo[t];
    uint4* dhi = (uint4*)(smem + S_WHI);
    uint4* dlo = (uint4*)(smem + S_WLO);
    #pragma unroll 4
    for (int i = tid; i < IMG_U4; i += GT) { dhi[i] = shi[i]; dlo[i] = slo[i]; }
}

// gather warp w owns image rows w*8 .. w*8+7
__device__ __forceinline__ void cvtStore(const uint4* v, uint8_t* dst, int warp, int lane) {
    #pragma unroll
    for (int rr = 0; rr < 8; rr++) {
        float4 f = *(const float4*)&v[rr];
        __nv_bfloat16 h0 = __float2bfloat16_rn(f.x), h1 = __float2bfloat16_rn(f.y);
        __nv_bfloat16 h2 = __float2bfloat16_rn(f.z), h3 = __float2bfloat16_rn(f.w);
        __nv_bfloat16 l0 = __float2bfloat16_rn(f.x - __bfloat162float(h0));
        __nv_bfloat16 l1 = __float2bfloat16_rn(f.y - __bfloat162float(h1));
        __nv_bfloat16 l2 = __float2bfloat16_rn(f.z - __bfloat162float(h2));
        __nv_bfloat16 l3 = __float2bfloat16_rn(f.w - __bfloat162float(h3));
        uint32_t offB = (uint32_t)(warp * 8 + rr) * LDB + (uint32_t)lane * 8;
        *(uint2*)(dst + offB)        = make_uint2(pkbf(h0, h1), pkbf(h2, h3));
        *(uint2*)(dst + A_LO + offB) = make_uint2(pkbf(l0, l1), pkbf(l2, l3));
    }
}

__global__ __launch_bounds__(GT, 1)
void k_gemm(const float* __restrict__ x,
            const float* __restrict__ b,
            float* __restrict__ out)
{
    extern __shared__ uint8_t smem[];
    const int tid  = threadIdx.x;
    const int warp = tid >> 5;
    const int lane = tid & 31;
    const int mw   = warp & 7;      // m-chunk
    const int nh   = warp >> 3;     // n-half

    const uint32_t sbase = smem_u32(smem);
    float* biasS = (float*)(smem + S_BIAS);
    int*   rowsS = (int*)(smem + S_ROWS);

    int tb[TT + 1], off[TT + 1];
    #pragma unroll
    for (int i = 0; i <= TT; i++) { tb[i] = g_tileBase[i]; off[i] = g_offsets[i]; }

    const int total = tb[TT];
    const int per   = (total + gridDim.x - 1) / gridDim.x;
    const int i0    = blockIdx.x * per;
    const int i1    = min(i0 + per, total);
    if (i0 >= i1) return;

    // lane-constant ldmatrix offsets (proven mapping from R3)
    const uint32_t aOff = (uint32_t)(mw * 16 + (lane & 15)) * LDB + (uint32_t)(lane >> 4) * 16;
    const uint32_t bOff = (uint32_t)(nh * 64 + (lane & 7) + ((lane & 16) ? 8 : 0)) * LDB
                        + (uint32_t)((lane >> 3) & 1) * 16;

    float acc[8][4];
    #pragma unroll
    for (int j = 0; j < 8; j++)
        #pragma unroll
        for (int q = 0; q < 4; q++) acc[j][q] = 0.f;

    int   cur_type = -1;
    uint4 v[8];

    // ---- prologue: stage tile i0 ----
    {
        int t = 0;
        #pragma unroll
        for (int s = 1; s < TT; s++) t += (i0 >= tb[s]);
        copyW(t, smem, tid); cur_type = t;
        int segStart = off[t] + (i0 - tb[t]) * TILE_M;
        int nr       = min(TILE_M, off[t + 1] - segStart);
        if (tid < DIM) {
            rowsS[(i0 & 1) * DIM + tid] = (tid < nr) ? g_perm[segStart + tid] : -1;
            biasS[(i0 & 1) * DIM + tid] = b[(size_t)t * DIM + tid];
        }
        int rown = -1;
        if (lane < 8) {
            int idx = warp * 8 + lane;
            rown = (idx < nr) ? g_perm[segStart + idx] : -1;
        }
        #pragma unroll
        for (int rr = 0; rr < 8; rr++) {
            int row = __shfl_sync(0xffffffffu, rown, rr);
            uint4 vv = make_uint4(0, 0, 0, 0);
            if (row >= 0) vv = ((const uint4*)x)[(size_t)row * 32 + lane];
            v[rr] = vv;
        }
        cvtStore(v, smem + ((i0 & 1) ? S_A1 : S_A0), warp, lane);
        __syncthreads();
    }

    for (int i = i0; i < i1; i++) {
        const int cb = i & 1;

        // ---- prefetch tile i+1 (rows->regs, rowsS/biasS into other buffer) ----
        int nt = -1;
        if (i + 1 < i1) {
            nt = 0;
            #pragma unroll
            for (int s = 1; s < TT; s++) nt += ((i + 1) >= tb[s]);
            int segStart = off[nt] + (i + 1 - tb[nt]) * TILE_M;
            int nr       = min(TILE_M, off[nt + 1] - segStart);
            if (tid < DIM) {
                rowsS[(cb ^ 1) * DIM + tid] = (tid < nr) ? g_perm[segStart + tid] : -1;
                biasS[(cb ^ 1) * DIM + tid] = b[(size_t)nt * DIM + tid];
            }
            int rown = -1;
            if (lane < 8) {
                int idx = warp * 8 + lane;
                rown = (idx < nr) ? g_perm[segStart + idx] : -1;
            }
            #pragma unroll
            for (int rr = 0; rr < 8; rr++) {
                int row = __shfl_sync(0xffffffffu, rown, rr);
                uint4 vv = make_uint4(0, 0, 0, 0);
                if (row >= 0) vv = ((const uint4*)x)[(size_t)row * 32 + lane];
                v[rr] = vv;
            }
        }

        // ---- MMA: 3 products x 8 k-steps x 4 n16-tiles (this warp's n-half) ----
        #pragma unroll
        for (int p = 0; p < 3; p++) {
            const uint32_t aBase = sbase + (cb ? S_A1 : S_A0) + (p == 2 ? A_LO : 0) + aOff;
            const uint32_t bBase = sbase + (p == 1 ? S_WLO : S_WHI) + bOff;
            #pragma unroll
            for (int kk = 0; kk < 8; kk++) {
                uint32_t a[4];
                ldsm4(a, aBase + kk * 32);
                #pragma unroll
                for (int jj = 0; jj < 4; jj++) {
                    uint32_t bb[4];
                    ldsm4(bb, bBase + (uint32_t)jj * (16 * LDB) + kk * 32);
                    mma16816(acc[2 * jj],     a, bb[0], bb[1]);
                    mma16816(acc[2 * jj + 1], a, bb[2], bb[3]);
                }
            }
        }

        // ---- stage tile i+1 into the other A buffer ----
        if (nt >= 0) {
            if (nt != cur_type) {               // rare: W reload needs mma readers done
                __syncthreads();
                copyW(nt, smem, tid);
                cur_type = nt;
            }
            cvtStore(v, smem + ((cb ^ 1) ? S_A1 : S_A0), warp, lane);
        }
        __syncthreads();

        // ---- epilogue tile i ----
        {
            const int g   = lane >> 2;
            const int r1  = rowsS[cb * DIM + mw * 16 + g];
            const int r2  = rowsS[cb * DIM + mw * 16 + 8 + g];
            const float* bS = biasS + cb * DIM;
            #pragma unroll
            for (int j = 0; j < 8; j++) {
                int col = nh * 64 + j * 8 + (lane & 3) * 2;
                float2 bb = *(const float2*)(bS + col);
                if (r1 >= 0)
                    *(float2*)(out + (size_t)r1 * DIM + col) =
                        make_float2(acc[j][0] + bb.x, acc[j][1] + bb.y);
                if (r2 >= 0)
                    *(float2*)(out + (size_t)r2 * DIM + col) =
                        make_float2(acc[j][2] + bb.x, acc[j][3] + bb.y);
                acc[j][0] = acc[j][1] = acc[j][2] = acc[j][3] = 0.f;
            }
        }
    }
}

// ---------------- launch ----------------
extern "C" void kernel_launch(void* const* d_in, const int* in_sizes, int n_in,
                              void* d_out, int out_size)
{
    const float* x      = (const float*)d_in[0];
    const int*   x_type = (const int*)d_in[1];
    const float* W      = (const float*)d_in[2];
    const float* b      = (const float*)d_in[3];
    float*       out    = (float*)d_out;

    const int N   = in_sizes[1];
    const int seg = (N + NB - 1) / NB;

    static int nsm = 0;
    if (!nsm) {
        cudaDeviceGetAttribute(&nsm, cudaDevAttrMultiProcessorCount, 0);
        if (nsm <= 0) nsm = 148;
        cudaFuncSetAttribute(k_gemm, cudaFuncAttributeMaxDynamicSharedMemorySize, S_TOTAL);
    }

    k_count<<<NB, BT>>>(x_type, N, seg);
    k_scan<<<1, 256>>>();
    k_scatter<<<NB, BT>>>(x_type, N, seg);
    k_prep<<<TT, 256>>>(W);
    k_gemm<<<nsm, GT, S_TOTAL>>>(x, b, out);
}

// round 7
// speedup vs baseline: 2.0690x; 1.1702x over previous
#include <cuda_runtime.h>
#include <cuda_bf16.h>
#include <cstdint>

// HeteLinear: out[n] = x[n] @ W[x_type[n]] + b[x_type[n]]
// N=262144, IN=OUT=128, T=8, fp32.
// Grouped GEMM on mma.sync HMMA bf16, 3-product bf16 hi/lo split.
// Warp-specialized persistent CTAs: 8 consumer warps (m32xn64 tiles, MMA+epilogue)
// + 8 producer warps (gather/convert/stage next tile). One syncthreads per tile.

#define NMAX    262144
#define TT      8
#define DIM     128
#define TILE_M  128
#define GT      512
#define NB      256                 // compaction blocks
#define BT      256
#define PREPB   32                  // prep blocks appended to k_pre grid
#define LDE     136                 // padded image row (bf16 elems): 272B
#define LDB     (LDE * 2)
#define IMG_BYTES (DIM * LDE * 2)   // 34816
#define IMG_U4    (IMG_BYTES / 16)

// gemm smem layout (bytes)
#define S_A0    0
#define A_LO    34816
#define S_A1    69632
#define S_WHI   139264
#define S_WLO   174080
#define S_BIAS  208896              // float[2][128]
#define S_ROWS  209920              // int[2][128]
#define S_TOTAL 210944

// ---------------- device globals ----------------
__device__ int g_bcount[TT * NB];
__device__ int g_bbase[TT * NB];
__device__ int g_offsets[TT + 1];
__device__ int g_tileBase[TT + 1];
__device__ int g_perm[NMAX];
__device__ __align__(16) uint8_t g_Whi[TT][IMG_BYTES];
__device__ __align__(16) uint8_t g_Wlo[TT][IMG_BYTES];

// ---------------- helpers ----------------
__device__ __forceinline__ uint32_t smem_u32(const void* p) {
    uint32_t a;
    asm("{ .reg .u64 t; cvta.to.shared.u64 t, %1; cvt.u32.u64 %0, t; }" : "=r"(a) : "l"(p));
    return a;
}
__device__ __forceinline__ void ldsm4(uint32_t (&r)[4], uint32_t addr) {
    asm volatile("ldmatrix.sync.aligned.m8n8.x4.shared.b16 {%0,%1,%2,%3}, [%4];"
                 : "=r"(r[0]), "=r"(r[1]), "=r"(r[2]), "=r"(r[3]) : "r"(addr));
}
__device__ __forceinline__ void mma16816(float (&c)[4], const uint32_t (&a)[4],
                                         uint32_t b0, uint32_t b1) {
    asm volatile("mma.sync.aligned.m16n8k16.row.col.f32.bf16.bf16.f32 "
                 "{%0,%1,%2,%3}, {%4,%5,%6,%7}, {%8,%9}, {%0,%1,%2,%3};"
                 : "+f"(c[0]), "+f"(c[1]), "+f"(c[2]), "+f"(c[3])
                 : "r"(a[0]), "r"(a[1]), "r"(a[2]), "r"(a[3]), "r"(b0), "r"(b1));
}
__device__ __forceinline__ uint32_t pkbf(__nv_bfloat16 a, __nv_bfloat16 b) {
    return (uint32_t)__bfloat16_as_ushort(a) | ((uint32_t)__bfloat16_as_ushort(b) << 16);
}

// ---------------- pre: count (blocks 0..NB-1) + W prep (blocks NB..NB+31) ----------------
__global__ void k_pre(const int* __restrict__ xt, const float* __restrict__ W,
                      int n, int seg) {
    __shared__ float ws[32][129];            // prep staging (also covers cnt)
    const int tid = threadIdx.x, lane = tid & 31;

    if (blockIdx.x < NB) {
        // -------- per-block type histogram, atomic-free --------
        const int bid = blockIdx.x;
        const int start = bid * seg, end = min(start + seg, n);
        __shared__ int cnt[TT];
        if (tid < TT) cnt[tid] = 0;
        __syncthreads();
        int rc[TT];
        #pragma unroll
        for (int t = 0; t < TT; t++) rc[t] = 0;
        const int rounds = (seg + BT - 1) / BT;
        for (int r = 0; r < rounds; r++) {
            int i = start + r * BT + tid;
            int m = (i < end) ? xt[i] : -1;
            #pragma unroll
            for (int t = 0; t < TT; t++)
                rc[t] += __popc(__ballot_sync(0xffffffffu, m == t));
        }
        if (lane == 0) {
            #pragma unroll
            for (int t = 0; t < TT; t++) atomicAdd(&cnt[t], rc[t]);
        }
        __syncthreads();
        if (tid < TT) g_bcount[tid * NB + bid] = cnt[tid];
    } else {
        // -------- W prep slice: type t, k-chunk kb (32 rows) --------
        const int sl = blockIdx.x - NB;
        const int t  = sl >> 2;
        const int kb = (sl & 3) * 32;
        #pragma unroll
        for (int j = 0; j < 16; j++) {
            int idx = tid + j * 256;
            int r = idx >> 7, col = idx & 127;
            ws[r][col] = W[((size_t)t * DIM + kb + r) * DIM + col];
        }
        __syncthreads();
        const int kk = tid & 15;
        #pragma unroll
        for (int j = 0; j < 8; j++) {
            int nn = (tid >> 4) + j * 16;
            float w0 = ws[2 * kk][nn], w1 = ws[2 * kk + 1][nn];
            __nv_bfloat16 h0 = __float2bfloat16_rn(w0), h1 = __float2bfloat16_rn(w1);
            __nv_bfloat16 l0 = __float2bfloat16_rn(w0 - __bfloat162float(h0));
            __nv_bfloat16 l1 = __float2bfloat16_rn(w1 - __bfloat162float(h1));
            uint32_t off = (uint32_t)nn * LDB + (uint32_t)(kb + 2 * kk) * 2;
            *(uint32_t*)(g_Whi[t] + off) = pkbf(h0, h1);
            *(uint32_t*)(g_Wlo[t] + off) = pkbf(l0, l1);
        }
    }
}

__global__ void k_scan() {
    const int tid = threadIdx.x, warp = tid >> 5, lane = tid & 31;
    __shared__ int tot[TT];
    if (warp < TT) {
        int s = 0;
        #pragma unroll
        for (int c = 0; c < NB / 32; c++) s += g_bcount[warp * NB + c * 32 + lane];
        #pragma unroll
        for (int o = 16; o; o >>= 1) s += __shfl_xor_sync(0xffffffffu, s, o);
        if (lane == 0) tot[warp] = s;
    }
    __syncthreads();
    if (tid == 0) {
        int o = 0, tbv = 0;
        g_offsets[0] = 0; g_tileBase[0] = 0;
        for (int t = 0; t < TT; t++) {
            o += tot[t];
            g_offsets[t + 1] = o;
            tbv += (tot[t] + TILE_M - 1) / TILE_M;
            g_tileBase[t + 1] = tbv;
        }
    }
    __syncthreads();
    if (warp < TT) {
        int run = g_offsets[warp];
        #pragma unroll
        for (int c = 0; c < NB / 32; c++) {
            int v = g_bcount[warp * NB + c * 32 + lane];
            int xsc = v;
            #pragma unroll
            for (int o = 1; o < 32; o <<= 1) {
                int y = __shfl_up_sync(0xffffffffu, xsc, o);
                if (lane >= o) xsc += y;
            }
            g_bbase[warp * NB + c * 32 + lane] = run + xsc - v;
            run += __shfl_sync(0xffffffffu, xsc, 31);
        }
    }
}

__global__ void k_scatter(const int* __restrict__ xt, int n, int seg) {
    const int bid = blockIdx.x, tid = threadIdx.x, lane = tid & 31;
    const int start = bid * seg, end = min(start + seg, n);
    __shared__ int cur[TT];
    if (tid < TT) cur[tid] = g_bbase[tid * NB + bid];
    __syncthreads();
    const int rounds = (seg + BT - 1) / BT;
    for (int r = 0; r < rounds; r++) {
        int i = start + r * BT + tid;
        int m = (i < end) ? xt[i] : -1;
        #pragma unroll
        for (int t = 0; t < TT; t++) {
            unsigned mask = __ballot_sync(0xffffffffu, m == t);
            if (mask) {
                int leader = __ffs(mask) - 1;
                int pos = 0;
                if (lane == leader) pos = atomicAdd(&cur[t], __popc(mask));
                pos = __shfl_sync(0xffffffffu, pos, leader);
                if (m == t) g_perm[pos + __popc(mask & ((1u << lane) - 1u))] = i;
            }
        }
    }
}

// ---------------- GEMM ----------------
__device__ __forceinline__ void copyW(int t, uint8_t* smem, int tid) {
    const uint4* shi = (const uint4*)g_Whi[t];
    const uint4* slo = (const uint4*)g_Wlo[t];
    uint4* dhi = (uint4*)(smem + S_WHI);
    uint4* dlo = (uint4*)(smem + S_WLO);
    #pragma unroll 4
    for (int i = tid; i < IMG_U4; i += GT) { dhi[i] = shi[i]; dlo[i] = slo[i]; }
}

// convert+store one x row (512B, lane-sliced) into hi/lo images at image row ir
__device__ __forceinline__ void cvtRow(uint4 vv, uint8_t* dst, int ir, int lane) {
    float4 f = *(const float4*)&vv;
    __nv_bfloat16 h0 = __float2bfloat16_rn(f.x), h1 = __float2bfloat16_rn(f.y);
    __nv_bfloat16 h2 = __float2bfloat16_rn(f.z), h3 = __float2bfloat16_rn(f.w);
    __nv_bfloat16 l0 = __float2bfloat16_rn(f.x - __bfloat162float(h0));
    __nv_bfloat16 l1 = __float2bfloat16_rn(f.y - __bfloat162float(h1));
    __nv_bfloat16 l2 = __float2bfloat16_rn(f.z - __bfloat162float(h2));
    __nv_bfloat16 l3 = __float2bfloat16_rn(f.w - __bfloat162float(h3));
    uint32_t offB = (uint32_t)ir * LDB + (uint32_t)lane * 8;
    *(uint2*)(dst + offB)        = make_uint2(pkbf(h0, h1), pkbf(h2, h3));
    *(uint2*)(dst + A_LO + offB) = make_uint2(pkbf(l0, l1), pkbf(l2, l3));
}

__global__ __launch_bounds__(GT, 1)
void k_gemm(const float* __restrict__ x,
            const float* __restrict__ b,
            float* __restrict__ out)
{
    extern __shared__ uint8_t smem[];
    const int tid  = threadIdx.x;
    const int warp = tid >> 5;
    const int lane = tid & 31;
    const bool consumer = (warp < 8);
    const int mw = warp & 3;        // consumer: m chunk of 32 rows
    const int nh = (warp >> 2) & 1; // consumer: n half (64 cols)
    const int pw = warp - 8;        // producer index 0..7

    const uint32_t sbase = smem_u32(smem);
    float* biasS = (float*)(smem + S_BIAS);
    int*   rowsS = (int*)(smem + S_ROWS);

    int tb[TT + 1], off[TT + 1];
    #pragma unroll
    for (int i = 0; i <= TT; i++) { tb[i] = g_tileBase[i]; off[i] = g_offsets[i]; }

    const int total = tb[TT];
    const int per   = (total + gridDim.x - 1) / gridDim.x;
    const int i0    = blockIdx.x * per;
    const int i1    = min(i0 + per, total);
    if (i0 >= i1) return;

    // consumer ldmatrix lane offsets (mapping proven in R3/R4)
    const uint32_t aOff = (uint32_t)(mw * 32 + (lane & 15)) * LDB + (uint32_t)(lane >> 4) * 16;
    const uint32_t bOff = (uint32_t)(nh * 64 + (lane & 7) + ((lane & 16) ? 8 : 0)) * LDB
                        + (uint32_t)((lane >> 3) & 1) * 16;

    float acc[2][8][4];
    #pragma unroll
    for (int s = 0; s < 2; s++)
        #pragma unroll
        for (int j = 0; j < 8; j++)
            #pragma unroll
            for (int q = 0; q < 4; q++) acc[s][j][q] = 0.f;

    int cur_type;

    // ---- prologue: stage tile i0 (all warps; each stages 8 rows) ----
    {
        int t = 0;
        #pragma unroll
        for (int s = 1; s < TT; s++) t += (i0 >= tb[s]);
        copyW(t, smem, tid); cur_type = t;
        int segStart = off[t] + (i0 - tb[t]) * TILE_M;
        int nr       = min(TILE_M, off[t + 1] - segStart);
        if (tid < DIM) {
            rowsS[(i0 & 1) * DIM + tid] = (tid < nr) ? g_perm[segStart + tid] : -1;
            biasS[(i0 & 1) * DIM + tid] = b[(size_t)t * DIM + tid];
        }
        int rown = -1;
        if (lane < 8) {
            int idx = warp * 8 + lane;
            rown = (idx < nr) ? g_perm[segStart + idx] : -1;
        }
        uint8_t* dst = smem + ((i0 & 1) ? S_A1 : S_A0);
        #pragma unroll
        for (int rr = 0; rr < 8; rr++) {
            int row = __shfl_sync(0xffffffffu, rown, rr);
            uint4 vv = make_uint4(0, 0, 0, 0);
            if (row >= 0) vv = ((const uint4*)x)[(size_t)row * 32 + lane];
            cvtRow(vv, dst, warp * 8 + rr, lane);
        }
        __syncthreads();
    }

    for (int i = i0; i < i1; i++) {
        const int cb = i & 1;
        // next-tile type (uniform across block, needed for the W-reload sync)
        int nt = cur_type;
        if (i + 1 < i1) {
            nt = 0;
            #pragma unroll
            for (int s = 1; s < TT; s++) nt += ((i + 1) >= tb[s]);
        }

        if (consumer) {
            // ---- MMA: 3 products x 8 k-steps, m32 x n64 ----
            #pragma unroll
            for (int p = 0; p < 3; p++) {
                const uint32_t aBase = sbase + (cb ? S_A1 : S_A0) + (p == 2 ? A_LO : 0) + aOff;
                const uint32_t bBase = sbase + (p == 1 ? S_WLO : S_WHI) + bOff;
                #pragma unroll
                for (int kk = 0; kk < 8; kk++) {
                    uint32_t a0[4], a1[4];
                    ldsm4(a0, aBase + kk * 32);
                    ldsm4(a1, aBase + 16 * LDB + kk * 32);
                    #pragma unroll
                    for (int jj = 0; jj < 4; jj++) {
                        uint32_t bb[4];
                        ldsm4(bb, bBase + (uint32_t)jj * (16 * LDB) + kk * 32);
                        mma16816(acc[0][2 * jj],     a0, bb[0], bb[1]);
                        mma16816(acc[0][2 * jj + 1], a0, bb[2], bb[3]);
                        mma16816(acc[1][2 * jj],     a1, bb[0], bb[1]);
                        mma16816(acc[1][2 * jj + 1], a1, bb[2], bb[3]);
                    }
                }
            }
            // ---- epilogue (before sync: rowsS/biasS slot cb is stable) ----
            const int g = lane >> 2;
            const float* bS = biasS + cb * DIM;
            #pragma unroll
            for (int s = 0; s < 2; s++) {
                const int rbase = mw * 32 + s * 16 + g;
                const int r1 = rowsS[cb * DIM + rbase];
                const int r2 = rowsS[cb * DIM + rbase + 8];
                #pragma unroll
                for (int j = 0; j < 8; j++) {
                    int col = nh * 64 + j * 8 + (lane & 3) * 2;
                    float2 bb = *(const float2*)(bS + col);
                    if (r1 >= 0)
                        *(float2*)(out + (size_t)r1 * DIM + col) =
                            make_float2(acc[s][j][0] + bb.x, acc[s][j][1] + bb.y);
                    if (r2 >= 0)
                        *(float2*)(out + (size_t)r2 * DIM + col) =
                            make_float2(acc[s][j][2] + bb.x, acc[s][j][3] + bb.y);
                    acc[s][j][0] = acc[s][j][1] = acc[s][j][2] = acc[s][j][3] = 0.f;
                }
            }
        } else if (i + 1 < i1) {
            // ---- producer: stage tile i+1 into buffer cb^1 ----
            int segStart = off[nt] + (i + 1 - tb[nt]) * TILE_M;
            int nr       = min(TILE_M, off[nt + 1] - segStart);
            int ptid = tid - 256;
            if (ptid < DIM) {
                rowsS[(cb ^ 1) * DIM + ptid] = (ptid < nr) ? g_perm[segStart + ptid] : -1;
                biasS[(cb ^ 1) * DIM + ptid] = b[(size_t)nt * DIM + ptid];
            }
            int rown = -1;
            if (lane < 16) {
                int idx = pw * 16 + lane;
                rown = (idx < nr) ? g_perm[segStart + idx] : -1;
            }
            uint8_t* dst = smem + ((cb ^ 1) ? S_A1 : S_A0);
            #pragma unroll
            for (int rr = 0; rr < 16; rr++) {
                int row = __shfl_sync(0xffffffffu, rown, rr);
                uint4 vv = make_uint4(0, 0, 0, 0);
                if (row >= 0) vv = ((const uint4*)x)[(size_t)row * 32 + lane];
                cvtRow(vv, dst, pw * 16 + rr, lane);
            }
        }

        __syncthreads();
        if (nt != cur_type) {     // rare W reload: consumers are done with tile i now
            copyW(nt, smem, tid);
            cur_type = nt;
            __syncthreads();
        }
    }
}

// ---------------- launch ----------------
extern "C" void kernel_launch(void* const* d_in, const int* in_sizes, int n_in,
                              void* d_out, int out_size)
{
    const float* x      = (const float*)d_in[0];
    const int*   x_type = (const int*)d_in[1];
    const float* W      = (const float*)d_in[2];
    const float* b      = (const float*)d_in[3];
    float*       out    = (float*)d_out;

    const int N   = in_sizes[1];
    const int seg = (N + NB - 1) / NB;

    static int nsm = 0;
    if (!nsm) {
        cudaDeviceGetAttribute(&nsm, cudaDevAttrMultiProcessorCount, 0);
        if (nsm <= 0) nsm = 148;
        cudaFuncSetAttribute(k_gemm, cudaFuncAttributeMaxDynamicSharedMemorySize, S_TOTAL);
    }

    k_pre<<<NB + PREPB, BT>>>(x_type, W, N, seg);
    k_scan<<<1, 256>>>();
    k_scatter<<<NB, BT>>>(x_type, N, seg);
    k_gemm<<<nsm, GT, S_TOTAL>>>(x, b, out);
}